// round 3
// baseline (speedup 1.0000x reference)
#include <cuda_runtime.h>
#include <math.h>

#define NN   8192
#define DIN  256
#define DH   128
#define DO   64
#define CAP  1024

// ---------------- scratch (static device allocations only) ----------------
__device__ float g_Wh1[(size_t)NN * DH];   // 4 MB
__device__ float g_h1 [(size_t)NN * DH];   // 4 MB
__device__ float g_Wh2[(size_t)NN * DO];   // 2 MB
__device__ float g_f1a[NN], g_f2a[NN];
__device__ float g_f1b[NN], g_f2b[NN];
__device__ int   g_nbr[(size_t)NN * CAP];  // 32 MB neighbor lists (reused by layer 2)
__device__ int   g_cnt[NN];
__device__ float g_cs1[DH], g_cs2[DO];     // column sums (empty-row fallback)
__device__ float g_fmax1, g_fmax2;

// ---------------- init ----------------
__global__ void k_init() {
    int t = threadIdx.x;
    if (t < DH) g_cs1[t] = 0.f;
    if (t < DO) g_cs2[t] = 0.f;
}

// ---------------- layer1 projection: Wh1 = X @ W1, f1/f2 = Wh1 @ a1 halves ----------------
__global__ __launch_bounds__(128) void k_wh1(const float* __restrict__ X,
                                             const float* __restrict__ W1,
                                             const float* __restrict__ a1) {
    __shared__ float xs[DIN];
    __shared__ float red[DH];
    int row = blockIdx.x, k = threadIdx.x;
    xs[k]       = X[(size_t)row * DIN + k];
    xs[k + 128] = X[(size_t)row * DIN + k + 128];
    __syncthreads();
    float acc = 0.f;
#pragma unroll 16
    for (int t = 0; t < DIN; t++) acc = fmaf(xs[t], W1[t * DH + k], acc);
    g_Wh1[(size_t)row * DH + k] = acc;

    red[k] = acc * a1[k];
    __syncthreads();
    for (int s = 64; s > 0; s >>= 1) { if (k < s) red[k] += red[k + s]; __syncthreads(); }
    if (k == 0) g_f1a[row] = red[0];
    __syncthreads();
    red[k] = acc * a1[DH + k];
    __syncthreads();
    for (int s = 64; s > 0; s >>= 1) { if (k < s) red[k] += red[k + s]; __syncthreads(); }
    if (k == 0) g_f2a[row] = red[0];
}

// ---------------- column sums of Wh (for empty-adjacency-row fallback) ----------------
__global__ void k_cs1() {
    int k = threadIdx.x; int r0 = blockIdx.x * 128;
    float s = 0.f;
    for (int r = r0; r < r0 + 128; r++) s += g_Wh1[(size_t)r * DH + k];
    atomicAdd(&g_cs1[k], s);
}
__global__ void k_cs2() {
    int k = threadIdx.x; int r0 = blockIdx.x * 128;
    float s = 0.f;
    for (int r = r0; r < r0 + 128; r++) s += g_Wh2[(size_t)r * DO + k];
    atomicAdd(&g_cs2[k], s);
}

// ---------------- global max of f2 (softmax shift) ----------------
__global__ void k_fmax(int sel) {
    __shared__ float red[256];
    int t = threadIdx.x;
    const float* f = sel ? g_f2b : g_f2a;
    float m = -3.4e38f;
    for (int i = t; i < NN; i += 256) m = fmaxf(m, f[i]);
    red[t] = m; __syncthreads();
    for (int s = 128; s > 0; s >>= 1) { if (t < s) red[t] = fmaxf(red[t], red[t + s]); __syncthreads(); }
    if (t == 0) { if (sel) g_fmax2 = red[0]; else g_fmax1 = red[0]; }
}

// ---------------- layer1 fused: adj scan -> nbr list, att1 (written to out), hp1, elu ----------------
__global__ __launch_bounds__(256) void k_att1(const float* __restrict__ adj,
                                              float* __restrict__ att) {
    __shared__ int   s_idx[CAP];
    __shared__ float s_p[CAP];
    __shared__ float s_red[256];
    __shared__ int   s_cnt;
    int row = blockIdx.x, tid = threadIdx.x;
    if (tid == 0) s_cnt = 0;
    __syncthreads();

    float f1 = g_f1a[row];
    float mm = f1 + g_fmax1;
    float c = mm > 0.f ? mm : 0.2f * mm;  // >= max_j e(i,j); keeps exp in (0,1]

    const float4* arow = (const float4*)(adj + (size_t)row * NN);
    float4*       orow = (float4*)(att + (size_t)row * NN);
    for (int v = tid; v < NN / 4; v += 256) {
        float4 a = arow[v];
        orow[v] = make_float4(0.f, 0.f, 0.f, 0.f);  // non-neighbors exactly 0 (matches exp underflow)
        if (a.x > 0.f) { int j = 4*v + 0; float e = f1 + g_f2a[j]; e = e > 0.f ? e : 0.2f * e;
                         int p = atomicAdd(&s_cnt, 1); if (p < CAP) { s_idx[p] = j; s_p[p] = __expf(e - c); } }
        if (a.y > 0.f) { int j = 4*v + 1; float e = f1 + g_f2a[j]; e = e > 0.f ? e : 0.2f * e;
                         int p = atomicAdd(&s_cnt, 1); if (p < CAP) { s_idx[p] = j; s_p[p] = __expf(e - c); } }
        if (a.z > 0.f) { int j = 4*v + 2; float e = f1 + g_f2a[j]; e = e > 0.f ? e : 0.2f * e;
                         int p = atomicAdd(&s_cnt, 1); if (p < CAP) { s_idx[p] = j; s_p[p] = __expf(e - c); } }
        if (a.w > 0.f) { int j = 4*v + 3; float e = f1 + g_f2a[j]; e = e > 0.f ? e : 0.2f * e;
                         int p = atomicAdd(&s_cnt, 1); if (p < CAP) { s_idx[p] = j; s_p[p] = __expf(e - c); } }
    }
    __syncthreads();
    int cnt = min(s_cnt, CAP);
    if (tid == 0) g_cnt[row] = cnt;

    float ps = 0.f;
    for (int t = tid; t < cnt; t += 256) ps += s_p[t];
    s_red[tid] = ps; __syncthreads();
    for (int s = 128; s > 0; s >>= 1) { if (tid < s) s_red[tid] += s_red[tid + s]; __syncthreads(); }
    float ssum = s_red[0];

    // persist neighbor list for layer 2 (saves the second 268MB adj scan)
    for (int t = tid; t < cnt; t += 256) g_nbr[(size_t)row * CAP + t] = s_idx[t];

    if (cnt == 0) {  // softmax of all -9e15 -> uniform 1/N; hp = mean of Wh1 rows
        for (int v = tid; v < NN; v += 256) att[(size_t)row * NN + v] = 1.0f / NN;
        if (tid < DH) {
            float hp = g_cs1[tid] * (1.0f / NN);
            g_h1[(size_t)row * DH + tid] = hp > 0.f ? hp : expm1f(hp);
        }
        return;
    }
    float inv = 1.f / ssum;
    for (int t = tid; t < cnt; t += 256)
        att[(size_t)row * NN + s_idx[t]] = s_p[t] * inv;

    // hp1[row][k] = (1/s) * sum_nbr p * Wh1[j][k]; 2 threads per column
    int k = tid & 127, half = tid >> 7;
    float acc = 0.f;
    for (int t = half; t < cnt; t += 2)
        acc += s_p[t] * g_Wh1[(size_t)s_idx[t] * DH + k];
    __syncthreads();
    s_red[tid] = acc; __syncthreads();
    if (half == 0) {
        float hp = (s_red[k] + s_red[k + 128]) * inv;
        g_h1[(size_t)row * DH + k] = hp > 0.f ? hp : expm1f(hp);  // elu (concat=True)
    }
}

// ---------------- layer2 projection: Wh2 = h1 @ W2, f1b/f2b ----------------
__global__ __launch_bounds__(64) void k_wh2(const float* __restrict__ W2,
                                            const float* __restrict__ a2) {
    __shared__ float xs[DH];
    __shared__ float red[DO];
    int row = blockIdx.x, k = threadIdx.x;
    xs[k]      = g_h1[(size_t)row * DH + k];
    xs[k + 64] = g_h1[(size_t)row * DH + k + 64];
    __syncthreads();
    float acc = 0.f;
#pragma unroll 16
    for (int t = 0; t < DH; t++) acc = fmaf(xs[t], W2[t * DO + k], acc);
    g_Wh2[(size_t)row * DO + k] = acc;

    red[k] = acc * a2[k];
    __syncthreads();
    for (int s = 32; s > 0; s >>= 1) { if (k < s) red[k] += red[k + s]; __syncthreads(); }
    if (k == 0) g_f1b[row] = red[0];
    __syncthreads();
    red[k] = acc * a2[DO + k];
    __syncthreads();
    for (int s = 32; s > 0; s >>= 1) { if (k < s) red[k] += red[k + s]; __syncthreads(); }
    if (k == 0) g_f2b[row] = red[0];
}

// ---------------- layer2 fused: reuse nbr list, softmax, h2 = att2 @ Wh2 ----------------
__global__ __launch_bounds__(128) void k_att2(float* __restrict__ h2) {
    __shared__ int   s_idx[CAP];
    __shared__ float s_p[CAP];
    __shared__ float s_red[128];
    int row = blockIdx.x, tid = threadIdx.x;
    int cnt = g_cnt[row];
    float f1 = g_f1b[row];
    float mm = f1 + g_fmax2;
    float c = mm > 0.f ? mm : 0.2f * mm;

    float ps = 0.f;
    for (int t = tid; t < cnt; t += 128) {
        int j = g_nbr[(size_t)row * CAP + t];
        float e = f1 + g_f2b[j]; e = e > 0.f ? e : 0.2f * e;
        float p = __expf(e - c);
        s_idx[t] = j; s_p[t] = p; ps += p;
    }
    s_red[tid] = ps; __syncthreads();
    for (int s = 64; s > 0; s >>= 1) { if (tid < s) s_red[tid] += s_red[tid + s]; __syncthreads(); }
    float ssum = s_red[0];

    if (cnt == 0) {
        if (tid < DO) h2[(size_t)row * DO + tid] = g_cs2[tid] * (1.0f / NN);
        return;
    }
    float inv = 1.f / ssum;
    int k = tid & 63, half = tid >> 6;
    float acc = 0.f;
    for (int t = half; t < cnt; t += 2)
        acc += s_p[t] * g_Wh2[(size_t)s_idx[t] * DO + k];
    __syncthreads();
    s_red[tid] = acc; __syncthreads();
    if (half == 0)
        h2[(size_t)row * DO + k] = (s_red[k] + s_red[k + 64]) * inv;  // concat=False: no elu
}

// ---------------- decoder: G = sigmoid(h2 @ h2^T) * row_mask ----------------
__global__ __launch_bounds__(256) void k_dec(const float* __restrict__ h2,
                                             float* __restrict__ G) {
    __shared__ __align__(16) float As[64][68];
    __shared__ __align__(16) float Bs[64][68];
    int tid = threadIdx.y * 16 + threadIdx.x;
    int m0 = blockIdx.y * 64, n0 = blockIdx.x * 64;
    for (int i = tid; i < 4096; i += 256) { int r = i >> 6, k = i & 63; As[k][r] = h2[(size_t)(m0 + r) * DO + k]; }
    for (int i = tid; i < 4096; i += 256) { int r = i >> 6, k = i & 63; Bs[k][r] = h2[(size_t)(n0 + r) * DO + k]; }
    __syncthreads();

    float acc[4][4] = {};
    int ty = threadIdx.y * 4, tx = threadIdx.x * 4;
#pragma unroll 8
    for (int k = 0; k < DO; k++) {
        float4 a = *(const float4*)&As[k][ty];
        float4 b = *(const float4*)&Bs[k][tx];
        acc[0][0] = fmaf(a.x, b.x, acc[0][0]); acc[0][1] = fmaf(a.x, b.y, acc[0][1]);
        acc[0][2] = fmaf(a.x, b.z, acc[0][2]); acc[0][3] = fmaf(a.x, b.w, acc[0][3]);
        acc[1][0] = fmaf(a.y, b.x, acc[1][0]); acc[1][1] = fmaf(a.y, b.y, acc[1][1]);
        acc[1][2] = fmaf(a.y, b.z, acc[1][2]); acc[1][3] = fmaf(a.y, b.w, acc[1][3]);
        acc[2][0] = fmaf(a.z, b.x, acc[2][0]); acc[2][1] = fmaf(a.z, b.y, acc[2][1]);
        acc[2][2] = fmaf(a.z, b.z, acc[2][2]); acc[2][3] = fmaf(a.z, b.w, acc[2][3]);
        acc[3][0] = fmaf(a.w, b.x, acc[3][0]); acc[3][1] = fmaf(a.w, b.y, acc[3][1]);
        acc[3][2] = fmaf(a.w, b.z, acc[3][2]); acc[3][3] = fmaf(a.w, b.w, acc[3][3]);
    }
#pragma unroll
    for (int r = 0; r < 4; r++) {
        int gi = m0 + ty + r;
        float mask = g_cnt[gi] > 0 ? 1.f : 0.f;
        float4 v;
        v.x = mask / (1.f + __expf(-acc[r][0]));
        v.y = mask / (1.f + __expf(-acc[r][1]));
        v.z = mask / (1.f + __expf(-acc[r][2]));
        v.w = mask / (1.f + __expf(-acc[r][3]));
        *(float4*)&G[(size_t)gi * NN + n0 + tx] = v;
    }
}

// ---------------- launch ----------------
extern "C" void kernel_launch(void* const* d_in, const int* in_sizes, int n_in,
                              void* d_out, int out_size) {
    const float* X   = (const float*)d_in[0];
    const float* adj = (const float*)d_in[1];
    const float* W1  = (const float*)d_in[2];
    const float* a1  = (const float*)d_in[3];
    const float* W2  = (const float*)d_in[4];
    const float* a2  = (const float*)d_in[5];

    float* out = (float*)d_out;
    float* h2  = out;                                  // [NN, DO]
    float* gen = out + (size_t)NN * DO;                // [NN, NN]
    float* att = gen + (size_t)NN * NN;                // [NN, NN]

    k_init<<<1, 128>>>();
    k_wh1<<<NN, 128>>>(X, W1, a1);
    k_cs1<<<64, 128>>>();
    k_fmax<<<1, 256>>>(0);
    k_att1<<<NN, 256>>>(adj, att);
    k_wh2<<<NN, 64>>>(W2, a2);
    k_cs2<<<64, 64>>>();
    k_fmax<<<1, 256>>>(1);
    k_att2<<<NN, 128>>>(h2);
    dim3 gdim(NN / 64, NN / 64), bdim(16, 16);
    k_dec<<<gdim, bdim>>>(h2, gen);
}